// round 3
// baseline (speedup 1.0000x reference)
#include <cuda_runtime.h>

#define NB   32
#define CCH  512
#define HWD  3136
#define LL   64
#define CTD  512
#define KTOT 576   // 561 padded to 576

// -------- scratch (device globals; no runtime allocation) --------
__device__ float g_tc[(size_t)NB * HWD * LL];      // logits -> softmaxed tc, layout (n, hw, l)
__device__ float g_part[NB * 14 * LL * 2];         // per-chunk online-softmax (m, s)
__device__ float g_ms[NB * LL * 2];                // merged (M, 1/S)
__device__ float g_Ap[4][(size_t)NB * CTD * LL];   // split-K partials of A (n, c, l)
__device__ float g_pcp[NB * LL * 49];              // pos-encoder conv output (n, l, 49)
__device__ float g_B[(size_t)NB * KTOT * LL];      // concat [tokens0; pos; zeros] (n, 576, l)
__device__ float g_wtcT[CCH * LL];                 // w_tc transposed (c, l)
__device__ float g_wtokT[KTOT * CTD];              // w_tok transposed + zero-padded (k, d)

// -------- tiny weight preprocessing --------
__global__ void k_tr_wtc(const float* __restrict__ w_tc) {
    int idx = blockIdx.x * 256 + threadIdx.x;          // 32768
    int c = idx >> 6, l = idx & 63;
    g_wtcT[idx] = w_tc[l * CCH + c];
}
__global__ void k_tr_wtok(const float* __restrict__ w_tok) {
    int idx = blockIdx.x * 256 + threadIdx.x;          // 294912
    int k = idx >> 9, d = idx & 511;
    g_wtokT[idx] = (k < 561) ? w_tok[d * 561 + k] : 0.0f;
}

// -------- K1: logits[n, hw, l] = (feat[n,:,hw] . w_tc[l,:] + b_tc[l]) / sqrt(512) --------
__global__ __launch_bounds__(256) void k_logits(const float* __restrict__ feat,
                                                const float* __restrict__ b_tc) {
    int hw0 = blockIdx.x * 64, n = blockIdx.y;
    __shared__ float Fs[16][64];   // [kc][hw]
    __shared__ float Ws[16][64];   // [kc][l]
    int t  = threadIdx.x;
    int tx4 = (t & 15) * 4, ty4 = (t >> 4) * 4;
    float acc[4][4] = {};
    const float* fb = feat + ((size_t)n * CCH) * HWD + hw0;
    for (int k0 = 0; k0 < CCH; k0 += 16) {
        int r = t >> 4, c4 = (t & 15) * 4;
        *(float4*)&Fs[r][c4] = *(const float4*)(fb + (size_t)(k0 + r) * HWD + c4);
        *(float4*)&Ws[r][c4] = *(const float4*)(g_wtcT + (size_t)(k0 + r) * LL + c4);
        __syncthreads();
#pragma unroll
        for (int kc = 0; kc < 16; ++kc) {
            float4 a = *(float4*)&Fs[kc][ty4];
            float4 b = *(float4*)&Ws[kc][tx4];
            float av[4] = {a.x, a.y, a.z, a.w}, bv[4] = {b.x, b.y, b.z, b.w};
#pragma unroll
            for (int i = 0; i < 4; ++i)
#pragma unroll
                for (int j = 0; j < 4; ++j) acc[i][j] += av[i] * bv[j];
        }
        __syncthreads();
    }
    const float inv = 0.044194173824159216f;   // 1/sqrt(512)
    float* ob = g_tc + ((size_t)n * HWD + hw0) * LL;
#pragma unroll
    for (int i = 0; i < 4; ++i) {
        float4 v;
        v.x = (acc[i][0] + b_tc[tx4 + 0]) * inv;
        v.y = (acc[i][1] + b_tc[tx4 + 1]) * inv;
        v.z = (acc[i][2] + b_tc[tx4 + 2]) * inv;
        v.w = (acc[i][3] + b_tc[tx4 + 3]) * inv;
        *(float4*)(ob + (size_t)(ty4 + i) * LL + tx4) = v;
    }
}

// -------- K2: per-(n, chunk) online-softmax partials over 224 hw rows --------
__global__ __launch_bounds__(256) void k_sm_partial() {
    int ch = blockIdx.x, n = blockIdx.y;
    int t = threadIdx.x, l = t & 63, r = t >> 6;     // 4 rows x 64 cols
    const float* p = g_tc + (size_t)n * HWD * LL + (size_t)(ch * 224) * LL;
    float m = -1e30f, s = 0.0f;
    for (int hw = r; hw < 224; hw += 4) {
        float x = p[hw * LL + l];
        float nm = fmaxf(m, x);
        s = s * __expf(m - nm) + __expf(x - nm);
        m = nm;
    }
    __shared__ float sm[256], ss[256];
    sm[t] = m; ss[t] = s;
    __syncthreads();
    if (t < 64) {
        float M = sm[t], S = ss[t];
#pragma unroll
        for (int q = 1; q < 4; ++q) {
            float m2 = sm[t + 64 * q], s2 = ss[t + 64 * q];
            float nm = fmaxf(M, m2);
            S = S * __expf(M - nm) + s2 * __expf(m2 - nm);
            M = nm;
        }
        g_part[((n * 14 + ch) * 64 + t) * 2 + 0] = M;
        g_part[((n * 14 + ch) * 64 + t) * 2 + 1] = S;
    }
}

// -------- K3: merge 14 chunk partials per (n,l) --------
__global__ void k_sm_merge() {
    int idx = blockIdx.x * 256 + threadIdx.x;        // 2048
    if (idx >= NB * LL) return;
    int n = idx >> 6, l = idx & 63;
    float M = -1e30f, S = 0.0f;
    for (int ch = 0; ch < 14; ++ch) {
        float m = g_part[((n * 14 + ch) * 64 + l) * 2 + 0];
        float s = g_part[((n * 14 + ch) * 64 + l) * 2 + 1];
        float nm = fmaxf(M, m);
        S = S * __expf(M - nm) + s * __expf(m - nm);
        M = nm;
    }
    g_ms[idx * 2 + 0] = M;
    g_ms[idx * 2 + 1] = 1.0f / S;
}

// -------- K4: normalize tc in place --------
__global__ __launch_bounds__(256) void k_sm_norm() {
    size_t i4 = ((size_t)blockIdx.x * 256 + threadIdx.x) * 4;   // total 6422528
    float4 v = *(float4*)(g_tc + i4);
    int n = (int)(i4 / ((size_t)HWD * LL));
    int l0 = (int)(i4 & 63);
    int b = (n * 64 + l0) * 2;
    v.x = __expf(v.x - g_ms[b + 0]) * g_ms[b + 1];
    v.y = __expf(v.y - g_ms[b + 2]) * g_ms[b + 3];
    v.z = __expf(v.z - g_ms[b + 4]) * g_ms[b + 5];
    v.w = __expf(v.w - g_ms[b + 6]) * g_ms[b + 7];
    *(float4*)(g_tc + i4) = v;
}

// -------- K5: A[n,c,l] = sum_hw feat[n,c,hw] * tc[n,hw,l], split-K into 4 parts --------
__global__ __launch_bounds__(256) void k_agemm(const float* __restrict__ feat) {
    int c0 = blockIdx.x * 64, part = blockIdx.y, n = blockIdx.z;
    int hwb = part * 784;
    __shared__ float Fs[16][64];   // [kc][c]
    __shared__ float Ts[16][64];   // [kc][l]
    int t = threadIdx.x;
    int tx4 = (t & 15) * 4, ty4 = (t >> 4) * 4;
    float acc[4][4] = {};
    const float* fb = feat + ((size_t)n * CCH + c0) * HWD + hwb;
    const float* tb = g_tc + ((size_t)n * HWD + hwb) * LL;
    for (int k0 = 0; k0 < 784; k0 += 16) {
        int ci = t >> 2, kq = (t & 3) * 4;
        float4 f = *(const float4*)(fb + (size_t)ci * HWD + k0 + kq);
        Fs[kq + 0][ci] = f.x; Fs[kq + 1][ci] = f.y;
        Fs[kq + 2][ci] = f.z; Fs[kq + 3][ci] = f.w;
        int r = t >> 4, lv = (t & 15) * 4;
        *(float4*)&Ts[r][lv] = *(const float4*)(tb + (size_t)(k0 + r) * LL + lv);
        __syncthreads();
#pragma unroll
        for (int kc = 0; kc < 16; ++kc) {
            float4 a = *(float4*)&Fs[kc][ty4];
            float4 b = *(float4*)&Ts[kc][tx4];
            float av[4] = {a.x, a.y, a.z, a.w}, bv[4] = {b.x, b.y, b.z, b.w};
#pragma unroll
            for (int i = 0; i < 4; ++i)
#pragma unroll
                for (int j = 0; j < 4; ++j) acc[i][j] += av[i] * bv[j];
        }
        __syncthreads();
    }
    float* ob = g_Ap[part] + ((size_t)n * CTD + c0) * LL;
#pragma unroll
    for (int i = 0; i < 4; ++i) {
        float4 v = {acc[i][0], acc[i][1], acc[i][2], acc[i][3]};
        *(float4*)(ob + (size_t)(ty4 + i) * LL + tx4) = v;
    }
}

// -------- K6: pos-encoder. pc image (n,l) is contiguous slice of g_tc; resize 14x14, conv3x3 s2 p1 -> 7x7 --------
__global__ void k_pos(const float* __restrict__ w_ds3, const float* __restrict__ b_ds3,
                      const float* __restrict__ w_ds1, const float* __restrict__ b_ds1) {
    int nl = blockIdx.x;                         // n*64 + l
    int n = nl >> 6, l = nl & 63;
    __shared__ float S[196];
    const float* base = g_tc + (size_t)n * HWD * LL + (size_t)l * HWD;
    for (int q = threadIdx.x; q < 196; q += 64) {
        int i = q / 14, j = q % 14;
        S[q] = base[i * 224 + j * 4];            // img[4i, 4j], row stride 56
    }
    __syncthreads();
    if (threadIdx.x < 49) {
        int oy = threadIdx.x / 7, ox = threadIdx.x % 7;
        float acc = 0.0f;
#pragma unroll
        for (int ky = 0; ky < 3; ++ky)
#pragma unroll
            for (int kx = 0; kx < 3; ++kx) {
                int iy = 2 * oy + ky - 1, ix = 2 * ox + kx - 1;
                if (iy >= 0 && iy < 14 && ix >= 0 && ix < 14)
                    acc += S[iy * 14 + ix] * w_ds3[ky * 3 + kx];
            }
        float v = (acc + b_ds3[0]) * w_ds1[0] + b_ds1[0];
        g_pcp[(size_t)nl * 49 + threadIdx.x] = v;
    }
}

// -------- K7a: grouped mix -> B rows [0,512) --------
__global__ __launch_bounds__(256) void k_mix(const float* __restrict__ w_val,
                                             const float* __restrict__ b_val) {
    int g = blockIdx.x, n = blockIdx.y;
    __shared__ float sA[32][64];
    __shared__ float sW[32][33];
    int t = threadIdx.x;
    size_t abase = ((size_t)n * CTD + g * 32) * LL;
    for (int q = t; q < 2048; q += 256) {
        float v = g_Ap[0][abase + q] + g_Ap[1][abase + q] +
                  g_Ap[2][abase + q] + g_Ap[3][abase + q];
        sA[q >> 6][q & 63] = v;
    }
    for (int q = t; q < 1024; q += 256) sW[q >> 5][q & 31] = w_val[g * 1024 + q];
    __syncthreads();
    for (int q = t; q < 2048; q += 256) {
        int d = q >> 6, l = q & 63;
        float acc = b_val[g * 32 + d];          // sum_hw tc == 1 exactly
#pragma unroll
        for (int c = 0; c < 32; ++c) acc += sW[d][c] * sA[c][l];
        g_B[((size_t)n * KTOT + g * 32 + d) * LL + l] = acc;
    }
}

// -------- K7b: pos rows -> B rows [512,576) (>=561 zero) --------
__global__ __launch_bounds__(256) void k_posrows(const float* __restrict__ w_pos,
                                                 const float* __restrict__ b_pos) {
    int n = blockIdx.x;
    __shared__ float sp[3136];    // (l,49)
    __shared__ float swp[2401];
    int t = threadIdx.x;
    for (int q = t; q < 3136; q += 256) sp[q] = g_pcp[(size_t)n * 3136 + q];
    for (int q = t; q < 2401; q += 256) swp[q] = w_pos[q];
    __syncthreads();
    for (int q = t; q < 4096; q += 256) {
        int p = q >> 6, l = q & 63;
        float v = 0.0f;
        if (p < 49) {
            v = b_pos[p];
            for (int c = 0; c < 49; ++c) v += swp[p * 49 + c] * sp[l * 49 + c];
        }
        g_B[((size_t)n * KTOT + 512 + p) * LL + l] = v;
    }
}

// -------- K8: out[n,d,l] = sum_k wtokT[k,d] * B[n,k,l] + b_tok[d] --------
__global__ __launch_bounds__(256) void k_final(const float* __restrict__ b_tok,
                                               float* __restrict__ out) {
    int d0 = blockIdx.x * 64, n = blockIdx.y;
    __shared__ float Ws[16][64];
    __shared__ float Bs[16][64];
    int t = threadIdx.x;
    int tx4 = (t & 15) * 4, ty4 = (t >> 4) * 4;
    float acc[4][4] = {};
    const float* bb = g_B + (size_t)n * KTOT * LL;
    for (int k0 = 0; k0 < KTOT; k0 += 16) {
        int r = t >> 4, v4 = (t & 15) * 4;
        *(float4*)&Ws[r][v4] = *(const float4*)(g_wtokT + (size_t)(k0 + r) * CTD + d0 + v4);
        *(float4*)&Bs[r][v4] = *(const float4*)(bb + (size_t)(k0 + r) * LL + v4);
        __syncthreads();
#pragma unroll
        for (int kc = 0; kc < 16; ++kc) {
            float4 a = *(float4*)&Ws[kc][ty4];
            float4 b = *(float4*)&Bs[kc][tx4];
            float av[4] = {a.x, a.y, a.z, a.w}, bv[4] = {b.x, b.y, b.z, b.w};
#pragma unroll
            for (int i = 0; i < 4; ++i)
#pragma unroll
                for (int j = 0; j < 4; ++j) acc[i][j] += av[i] * bv[j];
        }
        __syncthreads();
    }
#pragma unroll
    for (int i = 0; i < 4; ++i) {
        int d = d0 + ty4 + i;
        float bt = b_tok[d];
        float4 v = {acc[i][0] + bt, acc[i][1] + bt, acc[i][2] + bt, acc[i][3] + bt};
        *(float4*)(out + ((size_t)n * CTD + d) * LL + tx4) = v;
    }
}

extern "C" void kernel_launch(void* const* d_in, const int* in_sizes, int n_in,
                              void* d_out, int out_size) {
    const float* feat  = (const float*)d_in[0];
    const float* w_tc  = (const float*)d_in[1];
    const float* b_tc  = (const float*)d_in[2];
    const float* w_val = (const float*)d_in[3];
    const float* b_val = (const float*)d_in[4];
    const float* w_ds3 = (const float*)d_in[5];
    const float* b_ds3 = (const float*)d_in[6];
    const float* w_ds1 = (const float*)d_in[7];
    const float* b_ds1 = (const float*)d_in[8];
    const float* w_pos = (const float*)d_in[9];
    const float* b_pos = (const float*)d_in[10];
    const float* w_tok = (const float*)d_in[11];
    const float* b_tok = (const float*)d_in[12];
    float* out = (float*)d_out;

    k_tr_wtc<<<128, 256>>>(w_tc);
    k_tr_wtok<<<1152, 256>>>(w_tok);
    k_logits<<<dim3(49, 32), 256>>>(feat, b_tc);
    k_sm_partial<<<dim3(14, 32), 256>>>();
    k_sm_merge<<<8, 256>>>();
    k_sm_norm<<<6272, 256>>>();
    k_agemm<<<dim3(8, 4, 32), 256>>>(feat);
    k_pos<<<2048, 64>>>(w_ds3, b_ds3, w_ds1, b_ds1);
    k_mix<<<dim3(16, 32), 256>>>(w_val, b_val);
    k_posrows<<<32, 256>>>(w_pos, b_pos);
    k_final<<<dim3(8, 32), 256>>>(b_tok, out);
}

// round 4
// speedup vs baseline: 1.2998x; 1.2998x over previous
#include <cuda_runtime.h>

#define NB   32
#define CCH  512
#define HWD  3136
#define LL   64
#define CTD  512
#define KTOT 576   // 561 padded to 576

// -------- scratch (device globals; no runtime allocation) --------
__device__ float g_tc[(size_t)NB * HWD * LL];      // logits -> softmaxed tc, layout (n, hw, l)
__device__ float g_part[NB * 14 * LL * 2];         // per-chunk online-softmax (m, s)
__device__ float g_ms[NB * LL * 2];                // merged (M, 1/S)
__device__ float g_A[(size_t)NB * CTD * LL];       // A (n, c, l)
__device__ float g_pcp[NB * LL * 49];              // pos-encoder conv output (n, l, 49)
__device__ float g_B[(size_t)NB * KTOT * LL];      // concat [tokens0; pos; zeros] (n, 576, l)
__device__ float g_wtcT[CCH * LL];                 // w_tc transposed (c, l)
__device__ float g_wtokT[KTOT * CTD];              // w_tok transposed + zero-padded (k, d)

// -------- helpers --------
__device__ __forceinline__ unsigned f2tf(float x) {
    unsigned u; asm("cvt.rna.tf32.f32 %0, %1;" : "=r"(u) : "f"(x)); return u;
}
__device__ __forceinline__ float tfv(float x) { return __uint_as_float(f2tf(x)); }
__device__ __forceinline__ void mma8(float* c, const unsigned* a, const unsigned* b) {
    asm volatile(
        "mma.sync.aligned.m16n8k8.row.col.f32.tf32.tf32.f32 "
        "{%0,%1,%2,%3},{%4,%5,%6,%7},{%8,%9},{%0,%1,%2,%3};"
        : "+f"(c[0]), "+f"(c[1]), "+f"(c[2]), "+f"(c[3])
        : "r"(a[0]), "r"(a[1]), "r"(a[2]), "r"(a[3]), "r"(b[0]), "r"(b[1]));
}

// -------- tiny weight preprocessing --------
__global__ void k_tr_wtc(const float* __restrict__ w_tc) {
    int idx = blockIdx.x * 256 + threadIdx.x;          // 32768
    int c = idx >> 6, l = idx & 63;
    g_wtcT[idx] = w_tc[l * CCH + c];
}
__global__ void k_tr_wtok(const float* __restrict__ w_tok) {
    int idx = blockIdx.x * 256 + threadIdx.x;          // 294912
    int k = idx >> 9, d = idx & 511;
    g_wtokT[idx] = (k < 561) ? w_tok[d * 561 + k] : 0.0f;
}

#define SA1 136   // A_s stride for k-row layout  (k*8+m)%32 conflict-free
#define SA2 36    // A_s stride for m-row layout  (m*4+k)%32 conflict-free
#define SB  72    // B_s stride                   (k*8+n)%32 conflict-free

// -------- K1 (tensor): logits[n, hw, l] = (feat . w_tc + b_tc) / sqrt(512) --------
// D[m=hw 128][n=l 64], K=c 512. A_s[k][m] from feat rows (c, hw). B_s[k][n] from g_wtcT rows.
__global__ __launch_bounds__(256) void k_logits_mma(const float* __restrict__ feat,
                                                    const float* __restrict__ b_tc) {
    __shared__ __align__(16) float As[32 * SA1];
    __shared__ __align__(16) float Bs[32 * SB];
    int m0 = blockIdx.x * 128, n = blockIdx.y;
    int t = threadIdx.x, wid = t >> 5, lane = t & 31;
    int gid = lane >> 2, tig = lane & 3;
    int wm = wid >> 1, wn = wid & 1;
    const float* fb = feat + (size_t)n * CCH * HWD;
    float c[2][4][4] = {};

    for (int k0 = 0; k0 < CCH; k0 += 32) {
#pragma unroll
        for (int j = 0; j < 4; ++j) {                  // A: 32 k-rows x 128 m
            int idx = t + 256 * j;
            int r = idx >> 5, c4 = (idx & 31) * 4;
            int mg = m0 + c4; if (mg > HWD - 4) mg = HWD - 4;
            float4 v = *(const float4*)(fb + (size_t)(k0 + r) * HWD + mg);
            uint4 u = {f2tf(v.x), f2tf(v.y), f2tf(v.z), f2tf(v.w)};
            *(uint4*)&As[r * SA1 + c4] = u;
        }
#pragma unroll
        for (int j = 0; j < 2; ++j) {                  // B: 32 k-rows x 64 l
            int idx = t + 256 * j;
            int r = idx >> 4, c4 = (idx & 15) * 4;
            float4 v = *(const float4*)(g_wtcT + (size_t)(k0 + r) * LL + c4);
            uint4 u = {f2tf(v.x), f2tf(v.y), f2tf(v.z), f2tf(v.w)};
            *(uint4*)&Bs[r * SB + c4] = u;
        }
        __syncthreads();
#pragma unroll
        for (int ks = 0; ks < 4; ++ks) {
            int kb = ks * 8;
            unsigned a[2][4], b[4][2];
#pragma unroll
            for (int mi = 0; mi < 2; ++mi) {
                int r0 = wm * 32 + mi * 16 + gid;
                a[mi][0] = __float_as_uint(As[(kb + tig) * SA1 + r0]);
                a[mi][1] = __float_as_uint(As[(kb + tig) * SA1 + r0 + 8]);
                a[mi][2] = __float_as_uint(As[(kb + tig + 4) * SA1 + r0]);
                a[mi][3] = __float_as_uint(As[(kb + tig + 4) * SA1 + r0 + 8]);
            }
#pragma unroll
            for (int ni = 0; ni < 4; ++ni) {
                int nn = wn * 32 + ni * 8 + gid;
                b[ni][0] = __float_as_uint(Bs[(kb + tig) * SB + nn]);
                b[ni][1] = __float_as_uint(Bs[(kb + tig + 4) * SB + nn]);
            }
#pragma unroll
            for (int mi = 0; mi < 2; ++mi)
#pragma unroll
                for (int ni = 0; ni < 4; ++ni) mma8(c[mi][ni], a[mi], b[ni]);
        }
        __syncthreads();
    }
    const float inv = 0.044194173824159216f;   // 1/sqrt(512)
    float* ob = g_tc + (size_t)n * HWD * LL;
#pragma unroll
    for (int mi = 0; mi < 2; ++mi)
#pragma unroll
        for (int ni = 0; ni < 4; ++ni) {
            int col = wn * 32 + ni * 8 + tig * 2;
            float b0 = b_tc[col], b1 = b_tc[col + 1];
#pragma unroll
            for (int h = 0; h < 2; ++h) {
                int hw = m0 + wm * 32 + mi * 16 + gid + h * 8;
                if (hw < HWD) {
                    float2 v = {(c[mi][ni][h * 2] + b0) * inv,
                                (c[mi][ni][h * 2 + 1] + b1) * inv};
                    *(float2*)(ob + (size_t)hw * LL + col) = v;
                }
            }
        }
}

// -------- K2: per-(n, chunk) online-softmax partials over 224 hw rows --------
__global__ __launch_bounds__(256) void k_sm_partial() {
    int ch = blockIdx.x, n = blockIdx.y;
    int t = threadIdx.x, l = t & 63, r = t >> 6;     // 4 rows x 64 cols
    const float* p = g_tc + (size_t)n * HWD * LL + (size_t)(ch * 224) * LL;
    float m = -1e30f, s = 0.0f;
    for (int hw = r; hw < 224; hw += 4) {
        float x = p[hw * LL + l];
        float nm = fmaxf(m, x);
        s = s * __expf(m - nm) + __expf(x - nm);
        m = nm;
    }
    __shared__ float sm[256], ss[256];
    sm[t] = m; ss[t] = s;
    __syncthreads();
    if (t < 64) {
        float M = sm[t], S = ss[t];
#pragma unroll
        for (int q = 1; q < 4; ++q) {
            float m2 = sm[t + 64 * q], s2 = ss[t + 64 * q];
            float nm = fmaxf(M, m2);
            S = S * __expf(M - nm) + s2 * __expf(m2 - nm);
            M = nm;
        }
        g_part[((n * 14 + ch) * 64 + t) * 2 + 0] = M;
        g_part[((n * 14 + ch) * 64 + t) * 2 + 1] = S;
    }
}

// -------- K3: merge 14 chunk partials per (n,l) --------
__global__ void k_sm_merge() {
    int idx = blockIdx.x * 256 + threadIdx.x;        // 2048
    if (idx >= NB * LL) return;
    int n = idx >> 6, l = idx & 63;
    float M = -1e30f, S = 0.0f;
    for (int ch = 0; ch < 14; ++ch) {
        float m = g_part[((n * 14 + ch) * 64 + l) * 2 + 0];
        float s = g_part[((n * 14 + ch) * 64 + l) * 2 + 1];
        float nm = fmaxf(M, m);
        S = S * __expf(M - nm) + s * __expf(m - nm);
        M = nm;
    }
    g_ms[idx * 2 + 0] = M;
    g_ms[idx * 2 + 1] = 1.0f / S;
}

// -------- K4: normalize tc in place --------
__global__ __launch_bounds__(256) void k_sm_norm() {
    size_t i4 = ((size_t)blockIdx.x * 256 + threadIdx.x) * 4;
    float4 v = *(float4*)(g_tc + i4);
    int n = (int)(i4 / ((size_t)HWD * LL));
    int b = (n * 64 + (int)(i4 & 63)) * 2;
    v.x = __expf(v.x - g_ms[b + 0]) * g_ms[b + 1];
    v.y = __expf(v.y - g_ms[b + 2]) * g_ms[b + 3];
    v.z = __expf(v.z - g_ms[b + 4]) * g_ms[b + 5];
    v.w = __expf(v.w - g_ms[b + 6]) * g_ms[b + 7];
    *(float4*)(g_tc + i4) = v;
}

// -------- K5 (tensor): A[n,c,l] = sum_hw feat[n,c,hw] * tc[n,hw,l] --------
// D[m=c 128][n=l 64], K=hw 3136. A_s[m][k] from feat rows (c, hw). B_s[k][n] from g_tc rows.
__global__ __launch_bounds__(256) void k_agemm_mma(const float* __restrict__ feat) {
    __shared__ __align__(16) float As[128 * SA2];
    __shared__ __align__(16) float Bs[32 * SB];
    int c0 = blockIdx.x * 128, n = blockIdx.y;
    int t = threadIdx.x, wid = t >> 5, lane = t & 31;
    int gid = lane >> 2, tig = lane & 3;
    int wm = wid >> 1, wn = wid & 1;
    const float* fb = feat + ((size_t)n * CCH + c0) * HWD;
    const float* tb = g_tc + (size_t)n * HWD * LL;
    float c[2][4][4] = {};

#pragma unroll 1
    for (int k0 = 0; k0 < HWD; k0 += 32) {
#pragma unroll
        for (int j = 0; j < 4; ++j) {                  // A: 128 m-rows x 32 k
            int idx = t + 256 * j;
            int m = idx >> 3, k4 = (idx & 7) * 4;
            float4 v = *(const float4*)(fb + (size_t)m * HWD + k0 + k4);
            uint4 u = {f2tf(v.x), f2tf(v.y), f2tf(v.z), f2tf(v.w)};
            *(uint4*)&As[m * SA2 + k4] = u;
        }
#pragma unroll
        for (int j = 0; j < 2; ++j) {                  // B: 32 k-rows x 64 l
            int idx = t + 256 * j;
            int r = idx >> 4, c4 = (idx & 15) * 4;
            float4 v = *(const float4*)(tb + (size_t)(k0 + r) * LL + c4);
            uint4 u = {f2tf(v.x), f2tf(v.y), f2tf(v.z), f2tf(v.w)};
            *(uint4*)&Bs[r * SB + c4] = u;
        }
        __syncthreads();
#pragma unroll
        for (int ks = 0; ks < 4; ++ks) {
            int kb = ks * 8;
            unsigned a[2][4], b[4][2];
#pragma unroll
            for (int mi = 0; mi < 2; ++mi) {
                int r0 = wm * 32 + mi * 16 + gid;
                a[mi][0] = __float_as_uint(As[r0 * SA2 + kb + tig]);
                a[mi][1] = __float_as_uint(As[(r0 + 8) * SA2 + kb + tig]);
                a[mi][2] = __float_as_uint(As[r0 * SA2 + kb + tig + 4]);
                a[mi][3] = __float_as_uint(As[(r0 + 8) * SA2 + kb + tig + 4]);
            }
#pragma unroll
            for (int ni = 0; ni < 4; ++ni) {
                int nn = wn * 32 + ni * 8 + gid;
                b[ni][0] = __float_as_uint(Bs[(kb + tig) * SB + nn]);
                b[ni][1] = __float_as_uint(Bs[(kb + tig + 4) * SB + nn]);
            }
#pragma unroll
            for (int mi = 0; mi < 2; ++mi)
#pragma unroll
                for (int ni = 0; ni < 4; ++ni) mma8(c[mi][ni], a[mi], b[ni]);
        }
        __syncthreads();
    }
    float* ob = g_A + ((size_t)n * CTD + c0) * LL;
#pragma unroll
    for (int mi = 0; mi < 2; ++mi)
#pragma unroll
        for (int ni = 0; ni < 4; ++ni) {
            int col = wn * 32 + ni * 8 + tig * 2;
#pragma unroll
            for (int h = 0; h < 2; ++h) {
                int row = wm * 32 + mi * 16 + gid + h * 8;
                float2 v = {c[mi][ni][h * 2], c[mi][ni][h * 2 + 1]};
                *(float2*)(ob + (size_t)row * LL + col) = v;
            }
        }
}

// -------- K6: pos-encoder --------
__global__ void k_pos(const float* __restrict__ w_ds3, const float* __restrict__ b_ds3,
                      const float* __restrict__ w_ds1, const float* __restrict__ b_ds1) {
    int nl = blockIdx.x;                         // n*64 + l
    int n = nl >> 6, l = nl & 63;
    __shared__ float S[196];
    const float* base = g_tc + (size_t)n * HWD * LL + (size_t)l * HWD;
    for (int q = threadIdx.x; q < 196; q += 64) {
        int i = q / 14, j = q % 14;
        S[q] = base[i * 224 + j * 4];
    }
    __syncthreads();
    if (threadIdx.x < 49) {
        int oy = threadIdx.x / 7, ox = threadIdx.x % 7;
        float acc = 0.0f;
#pragma unroll
        for (int ky = 0; ky < 3; ++ky)
#pragma unroll
            for (int kx = 0; kx < 3; ++kx) {
                int iy = 2 * oy + ky - 1, ix = 2 * ox + kx - 1;
                if (iy >= 0 && iy < 14 && ix >= 0 && ix < 14)
                    acc += S[iy * 14 + ix] * w_ds3[ky * 3 + kx];
            }
        float v = (acc + b_ds3[0]) * w_ds1[0] + b_ds1[0];
        g_pcp[(size_t)nl * 49 + threadIdx.x] = v;
    }
}

// -------- K7a: grouped mix -> B rows [0,512) --------
__global__ __launch_bounds__(256) void k_mix(const float* __restrict__ w_val,
                                             const float* __restrict__ b_val) {
    int g = blockIdx.x, n = blockIdx.y;
    __shared__ float sA[32][64];
    __shared__ float sW[32][33];
    int t = threadIdx.x;
    size_t abase = ((size_t)n * CTD + g * 32) * LL;
    for (int q = t; q < 2048; q += 256) sA[q >> 6][q & 63] = g_A[abase + q];
    for (int q = t; q < 1024; q += 256) sW[q >> 5][q & 31] = w_val[g * 1024 + q];
    __syncthreads();
    for (int q = t; q < 2048; q += 256) {
        int d = q >> 6, l = q & 63;
        float acc = b_val[g * 32 + d];          // sum_hw tc == 1 exactly
#pragma unroll
        for (int c = 0; c < 32; ++c) acc += sW[d][c] * sA[c][l];
        g_B[((size_t)n * KTOT + g * 32 + d) * LL + l] = acc;
    }
}

// -------- K7b: pos rows -> B rows [512,576) (>=561 zero) --------
__global__ __launch_bounds__(256) void k_posrows(const float* __restrict__ w_pos,
                                                 const float* __restrict__ b_pos) {
    int n = blockIdx.x;
    __shared__ float sp[3136];    // (l,49)
    __shared__ float swp[2401];
    int t = threadIdx.x;
    for (int q = t; q < 3136; q += 256) sp[q] = g_pcp[(size_t)n * 3136 + q];
    for (int q = t; q < 2401; q += 256) swp[q] = w_pos[q];
    __syncthreads();
    for (int q = t; q < 4096; q += 256) {
        int p = q >> 6, l = q & 63;
        float v = 0.0f;
        if (p < 49) {
            v = b_pos[p];
            for (int c = 0; c < 49; ++c) v += swp[p * 49 + c] * sp[l * 49 + c];
        }
        g_B[((size_t)n * KTOT + 512 + p) * LL + l] = v;
    }
}

// -------- K8 (fp32, keeps error budget): out = wtokT^T @ B + b_tok --------
__global__ __launch_bounds__(256) void k_final(const float* __restrict__ b_tok,
                                               float* __restrict__ out) {
    int d0 = blockIdx.x * 64, n = blockIdx.y;
    __shared__ float Ws[16][64];
    __shared__ float Bs2[16][64];
    int t = threadIdx.x;
    int tx4 = (t & 15) * 4, ty4 = (t >> 4) * 4;
    float acc[4][4] = {};
    const float* bb = g_B + (size_t)n * KTOT * LL;
    for (int k0 = 0; k0 < KTOT; k0 += 16) {
        int r = t >> 4, v4 = (t & 15) * 4;
        *(float4*)&Ws[r][v4] = *(const float4*)(g_wtokT + (size_t)(k0 + r) * CTD + d0 + v4);
        *(float4*)&Bs2[r][v4] = *(const float4*)(bb + (size_t)(k0 + r) * LL + v4);
        __syncthreads();
#pragma unroll
        for (int kc = 0; kc < 16; ++kc) {
            float4 a = *(float4*)&Ws[kc][ty4];
            float4 b = *(float4*)&Bs2[kc][tx4];
            float av[4] = {a.x, a.y, a.z, a.w}, bv[4] = {b.x, b.y, b.z, b.w};
#pragma unroll
            for (int i = 0; i < 4; ++i)
#pragma unroll
                for (int j = 0; j < 4; ++j) acc[i][j] += av[i] * bv[j];
        }
        __syncthreads();
    }
#pragma unroll
    for (int i = 0; i < 4; ++i) {
        int d = d0 + ty4 + i;
        float bt = b_tok[d];
        float4 v = {acc[i][0] + bt, acc[i][1] + bt, acc[i][2] + bt, acc[i][3] + bt};
        *(float4*)(out + ((size_t)n * CTD + d) * LL + tx4) = v;
    }
}

extern "C" void kernel_launch(void* const* d_in, const int* in_sizes, int n_in,
                              void* d_out, int out_size) {
    const float* feat  = (const float*)d_in[0];
    const float* w_tc  = (const float*)d_in[1];
    const float* b_tc  = (const float*)d_in[2];
    const float* w_val = (const float*)d_in[3];
    const float* b_val = (const float*)d_in[4];
    const float* w_ds3 = (const float*)d_in[5];
    const float* b_ds3 = (const float*)d_in[6];
    const float* w_ds1 = (const float*)d_in[7];
    const float* b_ds1 = (const float*)d_in[8];
    const float* w_pos = (const float*)d_in[9];
    const float* b_pos = (const float*)d_in[10];
    const float* w_tok = (const float*)d_in[11];
    const float* b_tok = (const float*)d_in[12];
    float* out = (float*)d_out;

    k_tr_wtc<<<128, 256>>>(w_tc);
    k_tr_wtok<<<1152, 256>>>(w_tok);
    k_logits_mma<<<dim3(25, 32), 256>>>(feat, b_tc);
    k_sm_partial<<<dim3(14, 32), 256>>>();
    k_sm_merge<<<8, 256>>>();
    k_sm_norm<<<6272, 256>>>();
    k_agemm_mma<<<dim3(4, 32), 256>>>(feat);
    k_pos<<<2048, 64>>>(w_ds3, b_ds3, w_ds1, b_ds1);
    k_mix<<<dim3(16, 32), 256>>>(w_val, b_val);
    k_posrows<<<32, 256>>>(w_pos, b_pos);
    k_final<<<dim3(8, 32), 256>>>(b_tok, out);
}

// round 6
// speedup vs baseline: 1.9722x; 1.5173x over previous
#include <cuda_runtime.h>
#include <cstdint>

#define NB   32
#define CCH  512
#define HWD  3136
#define LL   64
#define CTD  512
#define KTOT 576   // 561 padded to 576

// -------- scratch (device globals; no runtime allocation) --------
__device__ float g_tc[(size_t)NB * HWD * LL];      // logits -> softmaxed tc, layout (n, hw, l)
__device__ float g_part[NB * 28 * LL * 2];         // per-chunk online-softmax (m, s)
__device__ float g_ms[NB * LL * 2];                // merged (M, 1/S)
__device__ float g_Ap[4][(size_t)NB * CTD * LL];   // split-K partials of A (n, c, l)
__device__ float g_pcp[NB * LL * 49];              // pos-encoder conv output (n, l, 49)
__device__ float g_B[(size_t)NB * KTOT * LL];      // concat [tokens0; pos; zeros] (n, 576, l)
__device__ float g_wtcT[CCH * LL];                 // w_tc transposed (c, l)
__device__ float g_wtokT[KTOT * CTD];              // w_tok transposed + zero-padded (k, d)

// -------- helpers --------
__device__ __forceinline__ unsigned f2tf(float x) {
    unsigned u; asm("cvt.rna.tf32.f32 %0, %1;" : "=r"(u) : "f"(x)); return u;
}
__device__ __forceinline__ void mma8(float* c, const unsigned* a, const unsigned* b) {
    asm volatile(
        "mma.sync.aligned.m16n8k8.row.col.f32.tf32.tf32.f32 "
        "{%0,%1,%2,%3},{%4,%5,%6,%7},{%8,%9},{%0,%1,%2,%3};"
        : "+f"(c[0]), "+f"(c[1]), "+f"(c[2]), "+f"(c[3])
        : "r"(a[0]), "r"(a[1]), "r"(a[2]), "r"(a[3]), "r"(b[0]), "r"(b[1]));
}
__device__ __forceinline__ uint32_t smem_u32(const void* p) {
    uint32_t a;
    asm("{ .reg .u64 t; cvta.to.shared.u64 t, %1; cvt.u32.u64 %0, t; }" : "=r"(a) : "l"(p));
    return a;
}
__device__ __forceinline__ void cpa16(uint32_t dst, const void* src) {
    asm volatile("cp.async.cg.shared.global [%0], [%1], 16;" :: "r"(dst), "l"(src));
}
#define CPA_COMMIT() asm volatile("cp.async.commit_group;" ::: "memory")
#define CPA_WAIT1()  asm volatile("cp.async.wait_group 1;" ::: "memory")
#define CPA_WAIT0()  asm volatile("cp.async.wait_group 0;" ::: "memory")

// -------- tiny weight preprocessing --------
__global__ void k_tr_wtc(const float* __restrict__ w_tc) {
    int idx = blockIdx.x * 256 + threadIdx.x;          // 32768
    int c = idx >> 6, l = idx & 63;
    g_wtcT[idx] = w_tc[l * CCH + c];
}
__global__ void k_tr_wtok(const float* __restrict__ w_tok) {
    int idx = blockIdx.x * 256 + threadIdx.x;          // 294912
    int k = idx >> 9, d = idx & 511;
    g_wtokT[idx] = (k < 561) ? w_tok[d * 561 + k] : 0.0f;
}

#define SA1 136   // K1 As stride (k-row layout), conflict-free frag loads
#define SA2 36    // K5 As stride (m-row layout), conflict-free frag loads
#define SB  72    // Bs stride, conflict-free frag loads

// -------- K1: logits[n, hw, l] = (feat . w_tc + b_tc) / sqrt(512) --------
// cp.async double-buffered, k-slab 16. D[m=hw 128][n=l 64], K=c 512 (32 slabs).
__global__ __launch_bounds__(256) void k_logits_mma(const float* __restrict__ feat,
                                                    const float* __restrict__ b_tc) {
    __shared__ __align__(16) float As[2][16 * SA1];
    __shared__ __align__(16) float Bs[2][16 * SB];
    int m0 = blockIdx.x * 128, n = blockIdx.y;
    int t = threadIdx.x, wid = t >> 5, lane = t & 31;
    int gid = lane >> 2, tig = lane & 3;
    int wm = wid >> 1, wn = wid & 1;
    const float* fb = feat + (size_t)n * CCH * HWD;
    uint32_t sA[2] = {smem_u32(&As[0][0]), smem_u32(&As[1][0])};
    uint32_t sBm[2] = {smem_u32(&Bs[0][0]), smem_u32(&Bs[1][0])};
    float c[2][4][4] = {};

    // A staging: 512 float4 per slab (r=k-row 0..15, c4 = m offset)
    int ar0 = t >> 5, ac4 = (t & 31) * 4;          // +8 rows for second issue
    int mg0 = m0 + ac4; if (mg0 > HWD - 4) mg0 = HWD - 4;
    // B staging: 256 float4 per slab
    int br = t >> 4, bc4 = (t & 15) * 4;

    // prologue: slab 0
    {
        cpa16(sA[0] + (ar0 * SA1 + ac4) * 4, fb + (size_t)ar0 * HWD + mg0);
        cpa16(sA[0] + ((ar0 + 8) * SA1 + ac4) * 4, fb + (size_t)(ar0 + 8) * HWD + mg0);
        cpa16(sBm[0] + (br * SB + bc4) * 4, g_wtcT + (size_t)br * LL + bc4);
        CPA_COMMIT();
    }
    for (int s = 0; s < 32; ++s) {
        if (s < 31) {
            int k1 = (s + 1) * 16, b1 = (s + 1) & 1;
            cpa16(sA[b1] + (ar0 * SA1 + ac4) * 4, fb + (size_t)(k1 + ar0) * HWD + mg0);
            cpa16(sA[b1] + ((ar0 + 8) * SA1 + ac4) * 4, fb + (size_t)(k1 + ar0 + 8) * HWD + mg0);
            cpa16(sBm[b1] + (br * SB + bc4) * 4, g_wtcT + (size_t)(k1 + br) * LL + bc4);
            CPA_COMMIT();
            CPA_WAIT1();
        } else {
            CPA_WAIT0();
        }
        __syncthreads();
        const float* Ab = As[s & 1];
        const float* Bb = Bs[s & 1];
#pragma unroll
        for (int ks = 0; ks < 2; ++ks) {
            int kb = ks * 8;
            unsigned a[2][4], b[4][2];
#pragma unroll
            for (int mi = 0; mi < 2; ++mi) {
                int r0 = wm * 32 + mi * 16 + gid;
                a[mi][0] = f2tf(Ab[(kb + tig) * SA1 + r0]);
                a[mi][1] = f2tf(Ab[(kb + tig) * SA1 + r0 + 8]);
                a[mi][2] = f2tf(Ab[(kb + tig + 4) * SA1 + r0]);
                a[mi][3] = f2tf(Ab[(kb + tig + 4) * SA1 + r0 + 8]);
            }
#pragma unroll
            for (int ni = 0; ni < 4; ++ni) {
                int nn = wn * 32 + ni * 8 + gid;
                b[ni][0] = f2tf(Bb[(kb + tig) * SB + nn]);
                b[ni][1] = f2tf(Bb[(kb + tig + 4) * SB + nn]);
            }
#pragma unroll
            for (int mi = 0; mi < 2; ++mi)
#pragma unroll
                for (int ni = 0; ni < 4; ++ni) mma8(c[mi][ni], a[mi], b[ni]);
        }
        __syncthreads();
    }
    const float inv = 0.044194173824159216f;   // 1/sqrt(512)
    float* ob = g_tc + (size_t)n * HWD * LL;
#pragma unroll
    for (int mi = 0; mi < 2; ++mi)
#pragma unroll
        for (int ni = 0; ni < 4; ++ni) {
            int col = wn * 32 + ni * 8 + tig * 2;
            float b0 = b_tc[col], b1 = b_tc[col + 1];
#pragma unroll
            for (int h = 0; h < 2; ++h) {
                int hw = m0 + wm * 32 + mi * 16 + gid + h * 8;
                if (hw < HWD) {
                    float2 v = {(c[mi][ni][h * 2] + b0) * inv,
                                (c[mi][ni][h * 2 + 1] + b1) * inv};
                    *(float2*)(ob + (size_t)hw * LL + col) = v;
                }
            }
        }
}

// -------- K2: per-(n, chunk) online-softmax partials over 112 hw rows --------
__global__ __launch_bounds__(256) void k_sm_partial() {
    int ch = blockIdx.x, n = blockIdx.y;
    int t = threadIdx.x, l = t & 63, r = t >> 6;     // 4 rows x 64 cols
    const float* p = g_tc + (size_t)n * HWD * LL + (size_t)(ch * 112) * LL;
    float m = -1e30f, s = 0.0f;
    for (int hw = r; hw < 112; hw += 4) {
        float x = p[hw * LL + l];
        float nm = fmaxf(m, x);
        s = s * __expf(m - nm) + __expf(x - nm);
        m = nm;
    }
    __shared__ float sm[256], ss[256];
    sm[t] = m; ss[t] = s;
    __syncthreads();
    if (t < 64) {
        float M = sm[t], S = ss[t];
#pragma unroll
        for (int q = 1; q < 4; ++q) {
            float m2 = sm[t + 64 * q], s2 = ss[t + 64 * q];
            float nm = fmaxf(M, m2);
            S = S * __expf(M - nm) + s2 * __expf(m2 - nm);
            M = nm;
        }
        g_part[((n * 28 + ch) * 64 + t) * 2 + 0] = M;
        g_part[((n * 28 + ch) * 64 + t) * 2 + 1] = S;
    }
}

// -------- K3: merge 28 chunk partials per (n,l) --------
__global__ void k_sm_merge() {
    int idx = blockIdx.x * 256 + threadIdx.x;        // 2048
    if (idx >= NB * LL) return;
    int n = idx >> 6, l = idx & 63;
    float M = -1e30f, S = 0.0f;
    for (int ch = 0; ch < 28; ++ch) {
        float m = g_part[((n * 28 + ch) * 64 + l) * 2 + 0];
        float s = g_part[((n * 28 + ch) * 64 + l) * 2 + 1];
        float nm = fmaxf(M, m);
        S = S * __expf(M - nm) + s * __expf(m - nm);
        M = nm;
    }
    g_ms[idx * 2 + 0] = M;
    g_ms[idx * 2 + 1] = 1.0f / S;
}

// -------- K4: normalize tc in place --------
__global__ __launch_bounds__(256) void k_sm_norm() {
    size_t i4 = ((size_t)blockIdx.x * 256 + threadIdx.x) * 4;
    float4 v = *(float4*)(g_tc + i4);
    int n = (int)(i4 / ((size_t)HWD * LL));
    int b = (n * 64 + (int)(i4 & 63)) * 2;
    v.x = __expf(v.x - g_ms[b + 0]) * g_ms[b + 1];
    v.y = __expf(v.y - g_ms[b + 2]) * g_ms[b + 3];
    v.z = __expf(v.z - g_ms[b + 4]) * g_ms[b + 5];
    v.w = __expf(v.w - g_ms[b + 6]) * g_ms[b + 7];
    *(float4*)(g_tc + i4) = v;
}

// -------- K5: A[n,c,l] = sum_hw feat[n,c,hw] * tc[n,hw,l], split-K 4, cp.async pipelined --------
// D[m=c 128][n=l 64], per part K=784 (49 slabs of 16). As m-major, Bs k-major.
__global__ __launch_bounds__(256) void k_agemm(const float* __restrict__ feat) {
    __shared__ __align__(16) float As[2][128 * SA2];
    __shared__ __align__(16) float Bs[2][16 * SB];
    int c0 = blockIdx.x * 128, part = blockIdx.y, n = blockIdx.z;
    int hwb = part * 784;
    int t = threadIdx.x, wid = t >> 5, lane = t & 31;
    int gid = lane >> 2, tig = lane & 3;
    int wm = wid >> 1, wn = wid & 1;
    const float* fa = feat + ((size_t)n * CCH + c0) * HWD + hwb;
    const float* tb = g_tc + ((size_t)n * HWD + hwb) * LL;
    uint32_t sA[2] = {smem_u32(&As[0][0]), smem_u32(&As[1][0])};
    uint32_t sBm[2] = {smem_u32(&Bs[0][0]), smem_u32(&Bs[1][0])};
    float c[2][4][4] = {};

    // A staging: 512 float4/slab: m = idx>>2 (0..127), k4 = (idx&3)*4
    int am = t >> 1, ak4 = (t & 1) * 8;            // 2 float4 per thread, adjacent k
    // B staging: 256 float4/slab
    int br = t >> 4, bc4 = (t & 15) * 4;

    {
        cpa16(sA[0] + (am * SA2 + ak4) * 4, fa + (size_t)am * HWD + ak4);
        cpa16(sA[0] + (am * SA2 + ak4 + 4) * 4, fa + (size_t)am * HWD + ak4 + 4);
        cpa16(sBm[0] + (br * SB + bc4) * 4, tb + (size_t)br * LL + bc4);
        CPA_COMMIT();
    }
    for (int s = 0; s < 49; ++s) {
        if (s < 48) {
            int k1 = (s + 1) * 16, b1 = (s + 1) & 1;
            cpa16(sA[b1] + (am * SA2 + ak4) * 4, fa + (size_t)am * HWD + k1 + ak4);
            cpa16(sA[b1] + (am * SA2 + ak4 + 4) * 4, fa + (size_t)am * HWD + k1 + ak4 + 4);
            cpa16(sBm[b1] + (br * SB + bc4) * 4, tb + (size_t)(k1 + br) * LL + bc4);
            CPA_COMMIT();
            CPA_WAIT1();
        } else {
            CPA_WAIT0();
        }
        __syncthreads();
        const float* Ab = As[s & 1];
        const float* Bb = Bs[s & 1];
#pragma unroll
        for (int ks = 0; ks < 2; ++ks) {
            int kb = ks * 8;
            unsigned a[2][4], b[4][2];
#pragma unroll
            for (int mi = 0; mi < 2; ++mi) {
                int r0 = wm * 32 + mi * 16 + gid;
                a[mi][0] = f2tf(Ab[r0 * SA2 + kb + tig]);
                a[mi][1] = f2tf(Ab[(r0 + 8) * SA2 + kb + tig]);
                a[mi][2] = f2tf(Ab[r0 * SA2 + kb + tig + 4]);
                a[mi][3] = f2tf(Ab[(r0 + 8) * SA2 + kb + tig + 4]);
            }
#pragma unroll
            for (int ni = 0; ni < 4; ++ni) {
                int nn = wn * 32 + ni * 8 + gid;
                b[ni][0] = f2tf(Bb[(kb + tig) * SB + nn]);
                b[ni][1] = f2tf(Bb[(kb + tig + 4) * SB + nn]);
            }
#pragma unroll
            for (int mi = 0; mi < 2; ++mi)
#pragma unroll
                for (int ni = 0; ni < 4; ++ni) mma8(c[mi][ni], a[mi], b[ni]);
        }
        __syncthreads();
    }
    float* ob = g_Ap[part] + ((size_t)n * CTD + c0) * LL;
#pragma unroll
    for (int mi = 0; mi < 2; ++mi)
#pragma unroll
        for (int ni = 0; ni < 4; ++ni) {
            int col = wn * 32 + ni * 8 + tig * 2;
#pragma unroll
            for (int h = 0; h < 2; ++h) {
                int row = wm * 32 + mi * 16 + gid + h * 8;
                float2 v = {c[mi][ni][h * 2], c[mi][ni][h * 2 + 1]};
                *(float2*)(ob + (size_t)row * LL + col) = v;
            }
        }
}

// -------- K6: pos-encoder (flat .view semantics on (n,hw,l) storage) --------
__global__ void k_pos(const float* __restrict__ w_ds3, const float* __restrict__ b_ds3,
                      const float* __restrict__ w_ds1, const float* __restrict__ b_ds1) {
    int nl = blockIdx.x;                         // n*64 + l
    int n = nl >> 6, l = nl & 63;
    __shared__ float S[196];
    const float* base = g_tc + (size_t)n * HWD * LL + (size_t)l * HWD;  // flat view slice
    for (int q = threadIdx.x; q < 196; q += 64) {
        int i = q / 14, j = q % 14;
        S[q] = base[i * 224 + j * 4];            // img[4i, 4j], row stride 56
    }
    __syncthreads();
    if (threadIdx.x < 49) {
        int oy = threadIdx.x / 7, ox = threadIdx.x % 7;
        float acc = 0.0f;
#pragma unroll
        for (int ky = 0; ky < 3; ++ky)
#pragma unroll
            for (int kx = 0; kx < 3; ++kx) {
                int iy = 2 * oy + ky - 1, ix = 2 * ox + kx - 1;
                if (iy >= 0 && iy < 14 && ix >= 0 && ix < 14)
                    acc += S[iy * 14 + ix] * w_ds3[ky * 3 + kx];
            }
        float v = (acc + b_ds3[0]) * w_ds1[0] + b_ds1[0];
        g_pcp[(size_t)nl * 49 + threadIdx.x] = v;
    }
}

// -------- K7a: grouped mix (sums split-K parts) -> B rows [0,512) --------
__global__ __launch_bounds__(256) void k_mix(const float* __restrict__ w_val,
                                             const float* __restrict__ b_val) {
    int g = blockIdx.x, n = blockIdx.y;
    __shared__ float sA[32][64];
    __shared__ float sW[32][33];
    int t = threadIdx.x;
    size_t abase = ((size_t)n * CTD + g * 32) * LL;
    for (int q = t; q < 2048; q += 256) {
        float v = g_Ap[0][abase + q] + g_Ap[1][abase + q] +
                  g_Ap[2][abase + q] + g_Ap[3][abase + q];
        sA[q >> 6][q & 63] = v;
    }
    for (int q = t; q < 1024; q += 256) sW[q >> 5][q & 31] = w_val[g * 1024 + q];
    __syncthreads();
    for (int q = t; q < 2048; q += 256) {
        int d = q >> 6, l = q & 63;
        float acc = b_val[g * 32 + d];          // sum_hw tc == 1 exactly
#pragma unroll
        for (int c = 0; c < 32; ++c) acc += sW[d][c] * sA[c][l];
        g_B[((size_t)n * KTOT + g * 32 + d) * LL + l] = acc;
    }
}

// -------- K7b: pos rows -> B rows [512,576) (>=561 zero) --------
__global__ __launch_bounds__(256) void k_posrows(const float* __restrict__ w_pos,
                                                 const float* __restrict__ b_pos) {
    int n = blockIdx.x;
    __shared__ float sp[3136];    // (l,49)
    __shared__ float swp[2401];
    int t = threadIdx.x;
    for (int q = t; q < 3136; q += 256) sp[q] = g_pcp[(size_t)n * 3136 + q];
    for (int q = t; q < 2401; q += 256) swp[q] = w_pos[q];
    __syncthreads();
    for (int q = t; q < 4096; q += 256) {
        int p = q >> 6, l = q & 63;
        float v = 0.0f;
        if (p < 49) {
            v = b_pos[p];
            for (int c = 0; c < 49; ++c) v += swp[p * 49 + c] * sp[l * 49 + c];
        }
        g_B[((size_t)n * KTOT + 512 + p) * LL + l] = v;
    }
}

// -------- K8 (fp32, keeps error budget): out = wtokT^T @ B + b_tok --------
__global__ __launch_bounds__(256) void k_final(const float* __restrict__ b_tok,
                                               float* __restrict__ out) {
    int d0 = blockIdx.x * 64, n = blockIdx.y;
    __shared__ float Ws[16][64];
    __shared__ float Bs2[16][64];
    int t = threadIdx.x;
    int tx4 = (t & 15) * 4, ty4 = (t >> 4) * 4;
    float acc[4][4] = {};
    const float* bb = g_B + (size_t)n * KTOT * LL;
    for (int k0 = 0; k0 < KTOT; k0 += 16) {
        int r = t >> 4, v4 = (t & 15) * 4;
        *(float4*)&Ws[r][v4] = *(const float4*)(g_wtokT + (size_t)(k0 + r) * CTD + d0 + v4);
        *(float4*)&Bs2[r][v4] = *(const float4*)(bb + (size_t)(k0 + r) * LL + v4);
        __syncthreads();
#pragma unroll
        for (int kc = 0; kc < 16; ++kc) {
            float4 a = *(float4*)&Ws[kc][ty4];
            float4 b = *(float4*)&Bs2[kc][tx4];
            float av[4] = {a.x, a.y, a.z, a.w}, bv[4] = {b.x, b.y, b.z, b.w};
#pragma unroll
            for (int i = 0; i < 4; ++i)
#pragma unroll
                for (int j = 0; j < 4; ++j) acc[i][j] += av[i] * bv[j];
        }
        __syncthreads();
    }
#pragma unroll
    for (int i = 0; i < 4; ++i) {
        int d = d0 + ty4 + i;
        float bt = b_tok[d];
        float4 v = {acc[i][0] + bt, acc[i][1] + bt, acc[i][2] + bt, acc[i][3] + bt};
        *(float4*)(out + ((size_t)n * CTD + d) * LL + tx4) = v;
    }
}

extern "C" void kernel_launch(void* const* d_in, const int* in_sizes, int n_in,
                              void* d_out, int out_size) {
    const float* feat  = (const float*)d_in[0];
    const float* w_tc  = (const float*)d_in[1];
    const float* b_tc  = (const float*)d_in[2];
    const float* w_val = (const float*)d_in[3];
    const float* b_val = (const float*)d_in[4];
    const float* w_ds3 = (const float*)d_in[5];
    const float* b_ds3 = (const float*)d_in[6];
    const float* w_ds1 = (const float*)d_in[7];
    const float* b_ds1 = (const float*)d_in[8];
    const float* w_pos = (const float*)d_in[9];
    const float* b_pos = (const float*)d_in[10];
    const float* w_tok = (const float*)d_in[11];
    const float* b_tok = (const float*)d_in[12];
    float* out = (float*)d_out;

    k_tr_wtc<<<128, 256>>>(w_tc);
    k_tr_wtok<<<1152, 256>>>(w_tok);
    k_logits_mma<<<dim3(25, 32), 256>>>(feat, b_tc);
    k_sm_partial<<<dim3(28, 32), 256>>>();
    k_sm_merge<<<8, 256>>>();
    k_sm_norm<<<6272, 256>>>();
    k_agemm<<<dim3(4, 4, 32), 256>>>(feat);
    k_pos<<<2048, 64>>>(w_ds3, b_ds3, w_ds1, b_ds1);
    k_mix<<<dim3(16, 32), 256>>>(w_val, b_val);
    k_posrows<<<32, 256>>>(w_pos, b_pos);
    k_final<<<dim3(8, 32), 256>>>(b_tok, out);
}